// round 7
// baseline (speedup 1.0000x reference)
#include <cuda_runtime.h>
#include <cuda_bf16.h>

#define HH  2048
#define DD  1024
#define TT  4096
#define G3H 6144   // 3*HH

#define NB      148            // persistent blocks
#define GB      74             // blocks per barrier group (one group per GRU)
#define NW      28             // warps per block (7 groups x 4 k-quarters)
#define THREADS (NW * 32)
#define REPS    4              // h replicas in L2

// ---------------- device scratch (allocation-free rule: __device__ globals) ---
__device__ float g_xp[2][TT][G3H];                 // ~201 MB precomputed input projections
__device__ __nv_bfloat16 g_xb[2][TT][DD];          // bf16 x
__device__ __nv_bfloat16 g_wb[2][G3H][DD];         // bf16 W_ih
__device__ char  g_wq[2][G3H][HH];                 // int8 quantized W_hh
__device__ float g_wdq[2][G3H];                    // per-row dequant factor
__device__ __align__(16) char g_hq[2][REPS][2][HH];// [buf][replica][gru][H] int8 h
__device__ float g_h32[2 * HH];                    // final fp32 h for the head
__device__ unsigned int g_bar2[2][64];             // padded per-group counters (256B apart)
__device__ float g_fc1[256];

// ---------------- prep: reset barriers, zero h0 (all replicas) ---------------
__global__ void prep_kernel() {
    if (threadIdx.x < 128) ((unsigned int*)g_bar2)[threadIdx.x] = 0u;
    for (int j = threadIdx.x; j < (int)(sizeof(g_hq[0]) / 4); j += blockDim.x)
        ((unsigned int*)g_hq[0])[j] = 0u;
}

// ---------------- convert x, W_ih to bf16 ------------------------------------
__global__ void conv_bf16(const float* __restrict__ x1, const float* __restrict__ x2,
                          const float* __restrict__ W1, const float* __restrict__ W2) {
    const long long idx    = (long long)blockIdx.x * blockDim.x + threadIdx.x;
    const long long stride = (long long)gridDim.x * blockDim.x;
    const long long NX = (long long)TT * DD;
    const long long NW_ = (long long)G3H * DD;
    for (long long i = idx; i < NX; i += stride) {
        ((__nv_bfloat16*)g_xb[0])[i] = __float2bfloat16(x1[i]);
        ((__nv_bfloat16*)g_xb[1])[i] = __float2bfloat16(x2[i]);
    }
    for (long long i = idx; i < NW_; i += stride) {
        ((__nv_bfloat16*)g_wb[0])[i] = __float2bfloat16(W1[i]);
        ((__nv_bfloat16*)g_wb[1])[i] = __float2bfloat16(W2[i]);
    }
}

// ---------------- quantize W_hh rows to int8 ---------------------------------
__global__ void quant_kernel(const float* __restrict__ W1, const float* __restrict__ W2) {
    const int bi  = blockIdx.x;
    const int gru = bi / G3H;
    const int row = bi % G3H;
    const float* __restrict__ src = (gru ? W2 : W1) + (size_t)row * HH;
    __shared__ float red[256];
    const int tid = threadIdx.x;

    float m = 0.f;
    for (int j = tid; j < HH; j += 256) m = fmaxf(m, fabsf(src[j]));
    red[tid] = m; __syncthreads();
    for (int o = 128; o; o >>= 1) { if (tid < o) red[tid] = fmaxf(red[tid], red[tid + o]); __syncthreads(); }
    m = red[0];
    const float inv = (m > 0.f) ? 127.f / m : 0.f;
    if (tid == 0) g_wdq[gru][row] = m / (127.f * 127.f);

    unsigned int* dst = (unsigned int*)&g_wq[gru][row][0];
#pragma unroll
    for (int v = 0; v < 2; v++) {
        const int e = tid * 8 + v * 4;
        unsigned int p = 0;
#pragma unroll
        for (int b = 0; b < 4; b++) {
            int q = __float2int_rn(src[e + b] * inv);
            q = max(-127, min(127, q));
            p |= ((unsigned int)(q & 0xff)) << (b * 8);
        }
        dst[e / 4] = p;
    }
}

// ---------------- xp GEMM via bf16 mma.sync ----------------------------------
__device__ __forceinline__ void ldsm4(unsigned int* r, const void* p) {
    unsigned int sa = (unsigned int)__cvta_generic_to_shared(p);
    asm volatile("ldmatrix.sync.aligned.m8n8.x4.shared.b16 {%0,%1,%2,%3}, [%4];"
                 : "=r"(r[0]), "=r"(r[1]), "=r"(r[2]), "=r"(r[3]) : "r"(sa));
}
__device__ __forceinline__ void mma16816(float* c, const unsigned int* a,
                                         unsigned int b0, unsigned int b1) {
    asm volatile("mma.sync.aligned.m16n8k16.row.col.f32.bf16.bf16.f32 "
                 "{%0,%1,%2,%3}, {%4,%5,%6,%7}, {%8,%9}, {%0,%1,%2,%3};"
                 : "+f"(c[0]), "+f"(c[1]), "+f"(c[2]), "+f"(c[3])
                 : "r"(a[0]), "r"(a[1]), "r"(a[2]), "r"(a[3]), "r"(b0), "r"(b1));
}

__global__ __launch_bounds__(256, 2)
void xp_gemm_mma(const float* __restrict__ bih1, const float* __restrict__ bih2) {
    __shared__ __nv_bfloat16 As[128][40];
    __shared__ __nv_bfloat16 Bs[128][40];

    const int gru = blockIdx.z;
    const int bm  = blockIdx.y * 128;
    const int bn  = blockIdx.x * 128;
    const __nv_bfloat16* __restrict__ Ag = &g_xb[gru][0][0];
    const __nv_bfloat16* __restrict__ Bg = &g_wb[gru][0][0];
    const float* __restrict__ bias = gru ? bih2 : bih1;

    const int tid  = threadIdx.x;
    const int warp = tid >> 5;
    const int lane = tid & 31;
    const int wm   = warp & 3;
    const int wn   = warp >> 2;

    float acc[2][8][4];
#pragma unroll
    for (int i = 0; i < 2; i++)
#pragma unroll
        for (int j = 0; j < 8; j++)
#pragma unroll
            for (int k = 0; k < 4; k++) acc[i][j][k] = 0.f;

    for (int k0 = 0; k0 < DD; k0 += 32) {
#pragma unroll
        for (int v = 0; v < 2; v++) {
            const int e  = tid + v * 256;
            const int r  = e >> 2;
            const int cc = (e & 3) * 8;
            *(uint4*)&As[r][cc] = *(const uint4*)(Ag + (size_t)(bm + r) * DD + k0 + cc);
            *(uint4*)&Bs[r][cc] = *(const uint4*)(Bg + (size_t)(bn + r) * DD + k0 + cc);
        }
        __syncthreads();

#pragma unroll
        for (int kk = 0; kk < 32; kk += 16) {
            unsigned int a[2][4], b[4][4];
            const int arow = (lane & 15);
            const int acol = kk + 8 * (lane >> 4);
#pragma unroll
            for (int mf = 0; mf < 2; mf++)
                ldsm4(a[mf], &As[wm * 32 + mf * 16 + arow][acol]);
#pragma unroll
            for (int nb = 0; nb < 4; nb++)
                ldsm4(b[nb], &Bs[wn * 64 + nb * 16 + arow][acol]);
#pragma unroll
            for (int mf = 0; mf < 2; mf++)
#pragma unroll
                for (int nb = 0; nb < 4; nb++) {
                    mma16816(acc[mf][nb * 2 + 0], a[mf], b[nb][0], b[nb][2]);
                    mma16816(acc[mf][nb * 2 + 1], a[mf], b[nb][1], b[nb][3]);
                }
        }
        __syncthreads();
    }

    float* __restrict__ C = &g_xp[gru][0][0];
#pragma unroll
    for (int nf = 0; nf < 8; nf++) {
        const int gn = bn + wn * 64 + nf * 8 + (lane & 3) * 2;
        const float b0 = __ldg(bias + gn);
        const float b1 = __ldg(bias + gn + 1);
#pragma unroll
        for (int mf = 0; mf < 2; mf++) {
            const int gm = bm + wm * 32 + mf * 16 + (lane >> 2);
            C[(size_t)gm * G3H + gn]           = acc[mf][nf][0] + b0;
            C[(size_t)gm * G3H + gn + 1]       = acc[mf][nf][1] + b1;
            C[(size_t)(gm + 8) * G3H + gn]     = acc[mf][nf][2] + b0;
            C[(size_t)(gm + 8) * G3H + gn + 1] = acc[mf][nf][3] + b1;
        }
    }
}

// ---------------- persistent GRU scan: 4-way k-split DP4A --------------------
// warp w: output-group g = w>>2 (4 outputs), k-quarter q = w&3 (512 elems)
__global__ __launch_bounds__(THREADS, 1)
void gru_scan(const float* __restrict__ bhh1, const float* __restrict__ bhh2) {
    __shared__ uint4 s_r[NW * 4 * 32];           // r-gate quarters: 56 KB
    __shared__ uint4 s_h[128];                   // this GRU's int8 h: 2 KB
    __shared__ __align__(16) int s_part[7 * 3 * 4 * 4];  // partial dots
    __shared__ float s_xp[2][28 * 3];            // prefetched xp (dbl buffered)
    __shared__ float s_scale[28][6];             // fr,fz,fn,br,bz,bn per output
    __shared__ float s_hown[28];                 // fp32 h carry per output

    const int tid  = threadIdx.x;
    const int w    = tid >> 5;
    const int lane = tid & 31;
    const int grp  = (blockIdx.x < GB) ? 0 : 1;
    const int blk  = blockIdx.x - grp * GB;
    const int gru  = grp;
    const int g    = w >> 2;
    const int q    = w & 3;
    const int i0   = blk * 28 + g * 4;           // first output of this warp's group
    const bool active = (i0 < HH);

    // ---- load weights: r quarter -> SMEM, z & n quarters -> registers ----
    uint4 zr[4], nr[4];
    if (active) {
#pragma unroll
        for (int oo = 0; oo < 4; oo++) {
            const int row = i0 + oo;
            s_r[(w * 4 + oo) * 32 + lane] =
                ((const uint4*)&g_wq[gru][row][q * 512])[lane];
            zr[oo] = ((const uint4*)&g_wq[gru][row + HH][q * 512])[lane];
            nr[oo] = ((const uint4*)&g_wq[gru][row + 2 * HH][q * 512])[lane];
        }
    }
    // ---- per-output constants + state to SMEM ----
    if (tid < 28) {
        const int i  = blk * 28 + tid;
        const int ic = (i < HH) ? i : 0;
        const float* __restrict__ bh = gru ? bhh2 : bhh1;
        s_scale[tid][0] = g_wdq[gru][ic];
        s_scale[tid][1] = g_wdq[gru][ic + HH];
        s_scale[tid][2] = g_wdq[gru][ic + 2 * HH];
        s_scale[tid][3] = bh[ic];
        s_scale[tid][4] = bh[ic + HH];
        s_scale[tid][5] = bh[ic + 2 * HH];
        s_hown[tid] = 0.f;
    }
    const float* __restrict__ xpg = &g_xp[gru][0][0];

    // ---- prefetch xp[0] via cp.async ----
    if (tid < 84) {
        const int idx  = tid / 3;
        const int gate = tid - idx * 3;
        int i = blk * 28 + idx; if (i >= HH) i = 0;
        unsigned int sa = (unsigned int)__cvta_generic_to_shared(&s_xp[0][tid]);
        const float* ga = xpg + i + gate * HH;
        asm volatile("cp.async.ca.shared.global [%0], [%1], 4;" :: "r"(sa), "l"(ga));
    }
    asm volatile("cp.async.commit_group;");

    for (int t = 0; t < TT; t++) {
        // ---- stage h (replica blk&3) + prefetch xp[t+1] ----
        if (tid < 128)
            s_h[tid] = __ldcg((const uint4*)g_hq[t & 1][blk & 3][gru] + tid);
        if (tid < 84 && t + 1 < TT) {
            const int idx  = tid / 3;
            const int gate = tid - idx * 3;
            int i = blk * 28 + idx; if (i >= HH) i = 0;
            unsigned int sa = (unsigned int)__cvta_generic_to_shared(&s_xp[(t + 1) & 1][tid]);
            const float* ga = xpg + (size_t)(t + 1) * G3H + i + gate * HH;
            asm volatile("cp.async.ca.shared.global [%0], [%1], 4;" :: "r"(sa), "l"(ga));
        }
        asm volatile("cp.async.commit_group;");
        asm volatile("cp.async.wait_group 1;");
        __syncthreads();                                   // s_h + s_xp[t&1] ready

        // ---- partial dots ----
        if (active) {
            const uint4 h4 = s_h[q * 32 + lane];
#pragma unroll
            for (int oo = 0; oo < 4; oo++) {
                const uint4 r4 = s_r[(w * 4 + oo) * 32 + lane];
                int ar = 0, az = 0, an = 0;
                ar = __dp4a((int)r4.x, (int)h4.x, ar);
                ar = __dp4a((int)r4.y, (int)h4.y, ar);
                ar = __dp4a((int)r4.z, (int)h4.z, ar);
                ar = __dp4a((int)r4.w, (int)h4.w, ar);
                az = __dp4a((int)zr[oo].x, (int)h4.x, az);
                az = __dp4a((int)zr[oo].y, (int)h4.y, az);
                az = __dp4a((int)zr[oo].z, (int)h4.z, az);
                az = __dp4a((int)zr[oo].w, (int)h4.w, az);
                an = __dp4a((int)nr[oo].x, (int)h4.x, an);
                an = __dp4a((int)nr[oo].y, (int)h4.y, an);
                an = __dp4a((int)nr[oo].z, (int)h4.z, an);
                an = __dp4a((int)nr[oo].w, (int)h4.w, an);
                ar = __reduce_add_sync(0xffffffffu, ar);
                az = __reduce_add_sync(0xffffffffu, az);
                an = __reduce_add_sync(0xffffffffu, an);
                if (lane == 0) {
                    s_part[((g * 3 + 0) * 4 + oo) * 4 + q] = ar;
                    s_part[((g * 3 + 1) * 4 + oo) * 4 + q] = az;
                    s_part[((g * 3 + 2) * 4 + oo) * 4 + q] = an;
                }
            }
        }
        __syncthreads();                                   // partials visible

        // ---- combine + epilogue: warp g' = w (<7), lanes 0..3 ----
        if (w < 7 && lane < 4) {
            const int idx = w * 4 + lane;
            const int i   = blk * 28 + idx;
            if (i < HH) {
                const int4 pr = *(const int4*)&s_part[((w * 3 + 0) * 4 + lane) * 4];
                const int4 pz = *(const int4*)&s_part[((w * 3 + 1) * 4 + lane) * 4];
                const int4 pn = *(const int4*)&s_part[((w * 3 + 2) * 4 + lane) * 4];
                const float hr = (float)(pr.x + pr.y + pr.z + pr.w) * s_scale[idx][0] + s_scale[idx][3];
                const float hz = (float)(pz.x + pz.y + pz.z + pz.w) * s_scale[idx][1] + s_scale[idx][4];
                const float hn = (float)(pn.x + pn.y + pn.z + pn.w) * s_scale[idx][2] + s_scale[idx][5];
                const float xr = s_xp[t & 1][idx * 3 + 0];
                const float xz = s_xp[t & 1][idx * 3 + 1];
                const float xn = s_xp[t & 1][idx * 3 + 2];
                const float r = __fdividef(1.f, 1.f + __expf(-(xr + hr)));
                const float z = __fdividef(1.f, 1.f + __expf(-(xz + hz)));
                float n;
                asm("tanh.approx.f32 %0, %1;" : "=f"(n) : "f"(xn + r * hn));
                float ho = s_hown[idx];
                ho = (1.f - z) * n + z * ho;
                s_hown[idx] = ho;
                int q8 = __float2int_rn(ho * 127.f);
                q8 = max(-127, min(127, q8));
#pragma unroll
                for (int rep = 0; rep < REPS; rep++)
                    g_hq[(t + 1) & 1][rep][gru][i] = (char)q8;
            }
        }
        __syncthreads();                                   // h stores done

        // ---- group barrier: RED release + relaxed poll + acquire fence ----
        if (tid == 0) {
            asm volatile("red.release.gpu.global.add.u32 [%0], %1;"
                         :: "l"(&g_bar2[grp][0]), "r"(1u) : "memory");
            const unsigned int target = (unsigned int)GB * (unsigned int)(t + 1);
            unsigned int v;
            do {
                asm volatile("ld.relaxed.gpu.global.u32 %0, [%1];"
                             : "=r"(v) : "l"(&g_bar2[grp][0]) : "memory");
            } while (v < target);
            asm volatile("fence.acq_rel.gpu;" ::: "memory");
        }
        __syncthreads();
    }

    if (tid < 28) {
        const int i = blk * 28 + tid;
        if (i < HH) g_h32[gru * HH + i] = s_hown[tid];
    }
}

// ---------------- head: fc1 (relu) -------------------------------------------
__global__ void head_fc1(const float* __restrict__ w, const float* __restrict__ b) {
    __shared__ float red[256];
    const int row = blockIdx.x, tid = threadIdx.x;
    const float* __restrict__ wr = w + (long long)row * (2 * HH);
    float s = 0.f;
    for (int j = tid; j < 2 * HH; j += 256) s += wr[j] * g_h32[j];
    red[tid] = s; __syncthreads();
    for (int o = 128; o; o >>= 1) { if (tid < o) red[tid] += red[tid + o]; __syncthreads(); }
    if (tid == 0) { const float v = red[0] + b[row]; g_fc1[row] = v > 0.f ? v : 0.f; }
}

// ---------------- head: fc2 + log_softmax ------------------------------------
__global__ void head_fc2(const float* __restrict__ w, const float* __restrict__ b,
                         float* __restrict__ out) {
    __shared__ float logits[3];
    const int tid = threadIdx.x;
    const int wr = tid >> 5, lane = tid & 31;
    float s = 0.f;
    for (int j = lane; j < 256; j += 32) s += w[wr * 256 + j] * g_fc1[j];
#pragma unroll
    for (int off = 16; off; off >>= 1) s += __shfl_down_sync(0xffffffffu, s, off);
    if (lane == 0) logits[wr] = s + b[wr];
    __syncthreads();
    if (tid == 0) {
        const float m = fmaxf(logits[0], fmaxf(logits[1], logits[2]));
        const float l = logf(expf(logits[0] - m) + expf(logits[1] - m) + expf(logits[2] - m));
        out[0] = logits[0] - m - l;
        out[1] = logits[1] - m - l;
        out[2] = logits[2] - m - l;
    }
}

// ---------------- launcher ----------------------------------------------------
extern "C" void kernel_launch(void* const* d_in, const int* in_sizes, int n_in,
                              void* d_out, int out_size) {
    const float* x1    = (const float*)d_in[0];
    const float* x2    = (const float*)d_in[1];
    const float* W_ih1 = (const float*)d_in[2];
    const float* W_hh1 = (const float*)d_in[3];
    const float* b_ih1 = (const float*)d_in[4];
    const float* b_hh1 = (const float*)d_in[5];
    const float* W_ih2 = (const float*)d_in[6];
    const float* W_hh2 = (const float*)d_in[7];
    const float* b_ih2 = (const float*)d_in[8];
    const float* b_hh2 = (const float*)d_in[9];
    const float* fc1_w = (const float*)d_in[10];
    const float* fc1_b = (const float*)d_in[11];
    const float* fc2_w = (const float*)d_in[12];
    const float* fc2_b = (const float*)d_in[13];
    float* out = (float*)d_out;

    prep_kernel<<<1, 256>>>();
    conv_bf16<<<1024, 256>>>(x1, x2, W_ih1, W_ih2);
    quant_kernel<<<2 * G3H, 256>>>(W_hh1, W_hh2);
    xp_gemm_mma<<<dim3(G3H / 128, TT / 128, 2), 256>>>(b_ih1, b_ih2);
    gru_scan<<<NB, THREADS>>>(b_hh1, b_hh2);
    head_fc1<<<256, 256>>>(fc1_w, fc1_b);
    head_fc2<<<1, 96>>>(fc2_w, fc2_b, out);
}